// round 13
// baseline (speedup 1.0000x reference)
#include <cuda_runtime.h>
#include <cstdint>

// AdaptiveSparseVoxels: expand N parents -> 8N children.
// Output (float32): [8N x 32] row-major features, then 8N morton-as-float.
// Row layout: px py pz size dens c0..c26 (32 floats = 128B)
//
// R13: stream-separated variant. Steady-state DRAM must absorb 310MB/replay
// (6.1 TB/s = 76% of spec) — near the mixed-R/W wall. This round splits the
// two write streams into two kernels so each drains a PURE sequential
// address range (better DRAM page locality / fewer bus turnarounds):
//   K1: feature rows only (268MB), R6 Phase-A mapping (warp-op = 512B
//       contiguous STG.128, lane j=i&7 column, rg=i>>3).
//   K2: morton array only (8MB), one child per thread, inputs re-read from
//       warm L2 (~4MB).

#define TPB 256
#define WPB 8              // warps per block
#define WP  4              // parents per warp
#define PPB (WPB * WP)     // 32 parents per block

__device__ __forceinline__ unsigned part1by2(unsigned n) {
    n &= 1023u;
    n = (n ^ (n << 16)) & 0xFF0000FFu;
    n = (n ^ (n << 8))  & 0x0300F00Fu;
    n = (n ^ (n << 4))  & 0x030C30C3u;
    n = (n ^ (n << 2))  & 0x09249249u;
    return n;
}

__device__ __forceinline__ unsigned coord_of(float p, float fres, int resm1) {
    // reference: ((p + 1) / 2 * res).astype(int32) then clip(0, res-1)
    float norm = __fmul_rn(__fmul_rn(__fadd_rn(p, 1.0f), 0.5f), fres);
    int c = (int)norm;                 // trunc toward zero == astype(int32)
    c = c < 0 ? 0 : (c > resm1 ? resm1 : c);
    return (unsigned)c;
}

// ===================== K1: feature rows (pure 268MB stream) =====================
__global__ void __launch_bounds__(TPB)
asv_feat_kernel(
    const float* __restrict__ positions,   // [N,3]
    const float* __restrict__ sizes,       // [N]
    const float* __restrict__ densities,   // [N]
    const float* __restrict__ colors,      // [N,27]
    float*       __restrict__ out,         // [8N*32]
    unsigned N)
{
    __shared__ __align__(16) float rec[PPB * 32];

    const unsigned tid   = threadIdx.x;
    const unsigned pbase = blockIdx.x * PPB;
    const unsigned nP    = (N - pbase < PPB) ? (N - pbase) : PPB;

    // ---- Stage parent records in OUTPUT layout @ stride 32 floats ----
    for (unsigned i = tid; i < nP * 27u; i += TPB) {
        unsigned p = i / 27u, c = i - p * 27u;
        rec[p * 32u + 5u + c] = colors[(pbase + p) * 27u + c];
    }
    if (tid < nP * 3u) {
        unsigned p = tid / 3u, c = tid - p * 3u;
        rec[p * 32u + c] = positions[(pbase + p) * 3u + c];
    }
    if (tid < nP) {
        rec[tid * 32u + 3u] = sizes[pbase + tid];
        rec[tid * 32u + 4u] = densities[pbase + tid];
    }
    __syncthreads();

    const unsigned lane = tid & 31u;
    const unsigned wid  = tid >> 5;
    const unsigned j    = lane & 7u;       // float4 column of the row
    const unsigned rg   = lane >> 3;       // row within 4-row group

    #pragma unroll
    for (unsigned w = 0; w < WP; w++) {
        const unsigned pl = wid * WP + w;
        if (pl >= nP) break;

        const float* r  = &rec[pl * 32u];
        const float4 v  = *reinterpret_cast<const float4*>(r + 4u * j);
        const float4 ps = *reinterpret_cast<const float4*>(r);  // bcast

        const float s  = ps.w;
        const float qd = 0.25f * s;        // exact
        const float hs = 0.5f  * s;        // exact

        float* ob = out + (size_t)(pbase + pl) * 256u;  // 8 rows * 32

        #pragma unroll
        for (unsigned t = 0; t < 2; t++) {
            const unsigned oct = 4u * t + rg;

            float4 sv = v;
            if (j == 0u) {
                sv.x = __fadd_rn(ps.x, (oct & 1u) ? qd : -qd);
                sv.y = __fadd_rn(ps.y, (oct & 2u) ? qd : -qd);
                sv.z = __fadd_rn(ps.z, (oct & 4u) ? qd : -qd);
                sv.w = hs;
            }
            __stcs(reinterpret_cast<float4*>(ob + oct * 32u + 4u * j), sv);
        }
    }
}

// ===================== K2: morton codes (pure 8MB stream) =====================
__global__ void __launch_bounds__(TPB)
asv_morton_kernel(
    const float* __restrict__ positions,   // [N,3]
    const float* __restrict__ sizes,       // [N]
    const int*   __restrict__ level_p,     // [1]
    float*       __restrict__ mout,        // [8N]
    unsigned nrows)                        // 8N
{
    const unsigned tid = blockIdx.x * TPB + threadIdx.x;
    if (tid >= nrows) return;

    const unsigned p   = tid >> 3;
    const unsigned oct = tid & 7u;

    const int   res   = 64 << __ldg(level_p);
    const float fres  = (float)res;
    const int   resm1 = res - 1;

    const float s  = __ldg(&sizes[p]);
    const float qd = 0.25f * s;            // exact
    float px = __fadd_rn(__ldg(&positions[p * 3u + 0u]), (oct & 1u) ? qd : -qd);
    float py = __fadd_rn(__ldg(&positions[p * 3u + 1u]), (oct & 2u) ? qd : -qd);
    float pz = __fadd_rn(__ldg(&positions[p * 3u + 2u]), (oct & 4u) ? qd : -qd);

    unsigned code = (part1by2(coord_of(pz, fres, resm1)) << 2)
                  + (part1by2(coord_of(py, fres, resm1)) << 1)
                  +  part1by2(coord_of(px, fres, resm1));

    __stcs(&mout[tid], (float)(int)code);  // exact: code < 2^21 at level 1
}

extern "C" void kernel_launch(void* const* d_in, const int* in_sizes, int n_in,
                              void* d_out, int out_size) {
    const float* positions = (const float*)d_in[0];
    const float* sizes     = (const float*)d_in[1];
    const float* densities = (const float*)d_in[2];
    const float* colors    = (const float*)d_in[3];
    const int*   level     = (const int*)d_in[4];

    unsigned N     = (unsigned)(in_sizes[0] / 3);
    unsigned nrows = N * 8u;

    float* out = (float*)d_out;

    unsigned fblocks = (N + PPB - 1) / PPB;
    asv_feat_kernel<<<fblocks, TPB>>>(
        positions, sizes, densities, colors, out, N);

    unsigned mblocks = (nrows + TPB - 1) / TPB;
    asv_morton_kernel<<<mblocks, TPB>>>(
        positions, sizes, level, out + (size_t)nrows * 32u, nrows);
}

// round 14
// speedup vs baseline: 1.1475x; 1.1475x over previous
#include <cuda_runtime.h>
#include <cstdint>

// AdaptiveSparseVoxels: expand N parents -> 8N children.  FINAL (R6 form).
// Output (float32): [8N x 32] row-major features, then 8N morton-as-float.
// Row layout: px py pz size dens c0..c26 (32 floats = 128B)
//
// Converged after 13 rounds: every alternative drain (STG.256, TMA bulk,
// TMA pipelined, STG+TMA hybrid, write-back policy, split-stream kernels)
// is equal or worse. Steady-state DRAM absorbs 310MB/replay at ~6.1 TB/s
// (76% of spec) — the L2->DRAM write drain is the roofline; SM-side
// resources all have >35% headroom. This is the fastest measured variant
// (50.88-50.91us wall, rel_err 0.0, reproduced).
//
// Phase A (stores): lane i -> column j = i&7 (float4 of a row), rg = i>>3.
//   Warp-op writes 4 consecutive rows x lane's float4 = 512B contiguous.
//   One parent = 8 rows = 2 ops; lane's column float4 loaded from smem once.
// Phase B (morton): full-lane repack — warp owns 4 parents x 8 children,
//   one morton per lane; contiguous 128B morton store per warp.

#define TPB 256
#define WPB 8              // warps per block
#define WP  4              // parents per warp
#define PPB (WPB * WP)     // 32 parents per block

__device__ __forceinline__ unsigned part1by2(unsigned n) {
    n &= 1023u;
    n = (n ^ (n << 16)) & 0xFF0000FFu;
    n = (n ^ (n << 8))  & 0x0300F00Fu;
    n = (n ^ (n << 4))  & 0x030C30C3u;
    n = (n ^ (n << 2))  & 0x09249249u;
    return n;
}

__device__ __forceinline__ unsigned coord_of(float p, float fres, int resm1) {
    // reference: ((p + 1) / 2 * res).astype(int32) then clip(0, res-1)
    float norm = __fmul_rn(__fmul_rn(__fadd_rn(p, 1.0f), 0.5f), fres);
    int c = (int)norm;                 // trunc toward zero == astype(int32)
    c = c < 0 ? 0 : (c > resm1 ? resm1 : c);
    return (unsigned)c;
}

__global__ void __launch_bounds__(TPB)
asv_expand_kernel(
    const float* __restrict__ positions,   // [N,3]
    const float* __restrict__ sizes,       // [N]
    const float* __restrict__ densities,   // [N]
    const float* __restrict__ colors,      // [N,27]
    const int*   __restrict__ level_p,     // [1]
    float*       __restrict__ out,         // [8N*32] + [8N] morton-as-float
    unsigned N, unsigned nrows)            // nrows = 8N
{
    __shared__ __align__(16) float rec[PPB * 32];

    const unsigned tid   = threadIdx.x;
    const unsigned pbase = blockIdx.x * PPB;
    const unsigned nP    = (N - pbase < PPB) ? (N - pbase) : PPB;

    // ---- Stage parent records in OUTPUT layout @ stride 32 floats ----
    for (unsigned i = tid; i < nP * 27u; i += TPB) {
        unsigned p = i / 27u, c = i - p * 27u;
        rec[p * 32u + 5u + c] = colors[(pbase + p) * 27u + c];
    }
    if (tid < nP * 3u) {
        unsigned p = tid / 3u, c = tid - p * 3u;
        rec[p * 32u + c] = positions[(pbase + p) * 3u + c];
    }
    if (tid < nP) {
        rec[tid * 32u + 3u] = sizes[pbase + tid];
        rec[tid * 32u + 4u] = densities[pbase + tid];
    }
    __syncthreads();

    const unsigned lane = tid & 31u;
    const unsigned wid  = tid >> 5;        // warp 0..7

    // ================= Phase A: feature-row stores =================
    {
        const unsigned j  = lane & 7u;     // float4 column of the row
        const unsigned rg = lane >> 3;     // row within 4-row group

        #pragma unroll
        for (unsigned w = 0; w < WP; w++) {
            const unsigned pl = wid * WP + w;
            if (pl >= nP) break;

            const float* r  = &rec[pl * 32u];
            const float4 v  = *reinterpret_cast<const float4*>(r + 4u * j);
            const float4 ps = *reinterpret_cast<const float4*>(r);  // bcast

            const float s  = ps.w;
            const float qd = 0.25f * s;    // exact
            const float hs = 0.5f  * s;    // exact

            float* ob = out + (size_t)(pbase + pl) * 256u;  // 8 rows * 32

            #pragma unroll
            for (unsigned t = 0; t < 2; t++) {
                const unsigned oct = 4u * t + rg;

                float4 sv = v;
                if (j == 0u) {
                    sv.x = __fadd_rn(ps.x, (oct & 1u) ? qd : -qd);
                    sv.y = __fadd_rn(ps.y, (oct & 2u) ? qd : -qd);
                    sv.z = __fadd_rn(ps.z, (oct & 4u) ? qd : -qd);
                    sv.w = hs;
                }
                __stcs(reinterpret_cast<float4*>(ob + oct * 32u + 4u * j), sv);
            }
        }
    }

    // ================= Phase B: morton, full-lane repack =================
    {
        const unsigned pl  = wid * WP + (lane >> 3); // parent local
        const unsigned oct = lane & 7u;

        if (pl < nP) {
            const int   res   = 64 << __ldg(level_p);
            const float fres  = (float)res;
            const int   resm1 = res - 1;

            const float4 ps = *reinterpret_cast<const float4*>(&rec[pl * 32u]);

            const float qd = 0.25f * ps.w;
            float px = __fadd_rn(ps.x, (oct & 1u) ? qd : -qd);
            float py = __fadd_rn(ps.y, (oct & 2u) ? qd : -qd);
            float pz = __fadd_rn(ps.z, (oct & 4u) ? qd : -qd);

            unsigned code = (part1by2(coord_of(pz, fres, resm1)) << 2)
                          + (part1by2(coord_of(py, fres, resm1)) << 1)
                          +  part1by2(coord_of(px, fres, resm1));

            // global row = (pbase+pl)*8 + oct; contiguous across the warp
            __stcs(out + (size_t)nrows * 32u + (size_t)(pbase + pl) * 8u + oct,
                   (float)(int)code);      // exact: code < 2^21 at level 1
        }
    }
}

extern "C" void kernel_launch(void* const* d_in, const int* in_sizes, int n_in,
                              void* d_out, int out_size) {
    const float* positions = (const float*)d_in[0];
    const float* sizes     = (const float*)d_in[1];
    const float* densities = (const float*)d_in[2];
    const float* colors    = (const float*)d_in[3];
    const int*   level     = (const int*)d_in[4];

    unsigned N     = (unsigned)(in_sizes[0] / 3);
    unsigned nrows = N * 8u;

    unsigned blocks = (N + PPB - 1) / PPB;
    asv_expand_kernel<<<blocks, TPB>>>(
        positions, sizes, densities, colors, level,
        (float*)d_out, N, nrows);
}